// round 4
// baseline (speedup 1.0000x reference)
#include <cuda_runtime.h>
#include <cstdint>

// Varlen causal GQA flash attention, TF32 mma.sync — round 4.
// CTA = (seq, head, 64-query tile), 4 warps, warp w owns Q rows [w*16, w*16+16).
// 2 CTAs/SM co-resident -> load/compute overlap across CTAs.
// QK loop ordered ks-outer/nt-inner (8 independent accumulator chains).
// Per-warp causal cap skips masked MMAs in the diagonal tile.

#define TQ 64
#define TK 64
#define DH 128
#define NT 128
#define QSTRIDE 4096   // 32 heads * 128
#define KSTRIDE 1024   // 8 kv heads * 128

#define KPAD 132       // K row stride (floats): conflict-free QK B-frag loads
#define VPAD 136       // V row stride (floats): conflict-free PV B-frag loads
#define PPAD 76        // P row stride (floats): conflict-free PV A-frag loads

#define K_OFF  0
#define V_OFF  (TK * KPAD)                  // 8448
#define P_OFF  (V_OFF + TK * VPAD)          // 17152
#define PS_PER_WARP (16 * PPAD)             // 1216
#define SMEM_FLOATS (P_OFF + 4 * PS_PER_WARP)
#define SMEM_BYTES  (SMEM_FLOATS * 4)       // 88064

static __device__ __forceinline__ uint32_t cvt_tf32(float f) {
    uint32_t u;
    asm("cvt.rna.tf32.f32 %0, %1;" : "=r"(u) : "f"(f));
    return u;
}
static __device__ __forceinline__ float exp2f_fast(float x) {
    float y; asm("ex2.approx.ftz.f32 %0, %1;" : "=f"(y) : "f"(x)); return y;
}
// non-volatile: pure register op, let ptxas schedule freely
static __device__ __forceinline__ void mma_tf32(float c[4], const uint32_t a[4],
                                                const uint32_t b[2]) {
    asm("mma.sync.aligned.m16n8k8.row.col.f32.tf32.tf32.f32 "
        "{%0,%1,%2,%3}, {%4,%5,%6,%7}, {%8,%9}, {%0,%1,%2,%3};"
        : "+f"(c[0]), "+f"(c[1]), "+f"(c[2]), "+f"(c[3])
        : "r"(a[0]), "r"(a[1]), "r"(a[2]), "r"(a[3]), "r"(b[0]), "r"(b[1]));
}

__global__ __launch_bounds__(NT, 2)
void fa_tf32_mma_kernel(const float* __restrict__ q, const float* __restrict__ k,
                        const float* __restrict__ v, const int* __restrict__ cu,
                        float* __restrict__ out)
{
    extern __shared__ float smem[];
    float* Ks = smem + K_OFF;
    float* Vs = smem + V_OFF;

    const int seq  = blockIdx.z;
    const int head = blockIdx.y;
    const int q0   = blockIdx.x * TQ;
    const int s0   = cu[seq];
    const int L    = cu[seq + 1] - s0;
    if (q0 >= L) return;

    const int kvh  = head >> 2;
    const int tid  = threadIdx.x;
    const int wid  = tid >> 5;
    const int lane = tid & 31;
    const int g    = lane >> 2;   // group id (row within fragment)
    const int tig  = lane & 3;    // thread in group

    float* Ps = smem + P_OFF + wid * PS_PER_WARP;

    const float scale = 0.08838834764831845f * 1.4426950408889634f; // *log2e

    // ---- Q fragments: 16 k-steps x 4 regs, tf32, loaded once ----
    uint32_t qa[16][4];
    {
        const int r0 = q0 + wid * 16 + g;
        const int r1 = r0 + 8;
        const bool ok0 = r0 < L, ok1 = r1 < L;
        const float* p0 = q + (size_t)(s0 + r0) * QSTRIDE + head * DH;
        const float* p1 = q + (size_t)(s0 + r1) * QSTRIDE + head * DH;
        #pragma unroll
        for (int ks = 0; ks < 16; ks++) {
            const int c = ks * 8 + tig;
            qa[ks][0] = cvt_tf32(ok0 ? p0[c]     * scale : 0.f);
            qa[ks][1] = cvt_tf32(ok1 ? p1[c]     * scale : 0.f);
            qa[ks][2] = cvt_tf32(ok0 ? p0[c + 4] * scale : 0.f);
            qa[ks][3] = cvt_tf32(ok1 ? p1[c + 4] * scale : 0.f);
        }
    }

    float o[16][4];
    #pragma unroll
    for (int nt = 0; nt < 16; nt++)
        #pragma unroll
        for (int r = 0; r < 4; r++) o[nt][r] = 0.f;
    float lsum0 = 0.f, lsum1 = 0.f;

    const int qg_max = min(q0 + TQ - 1, L - 1);
    const int nkt    = qg_max / TK + 1;
    const float* kbase = k + (size_t)s0 * KSTRIDE + kvh * DH;
    const float* vbase = v + (size_t)s0 * KSTRIDE + kvh * DH;

    const int qrow0 = q0 + wid * 16 + g;
    const int qrow1 = qrow0 + 8;
    const int wrow_max = min(q0 + wid * 16 + 15, L - 1); // warp's last valid q row

    for (int t = 0; t < nkt; t++) {
        const int k0 = t * TK;
        if (t > 0) __syncthreads();

        // ---- load K and V tiles (tf32-converted), zero padded rows ----
        for (int i = tid; i < TK * 32; i += NT) {
            const int r  = i >> 5;
            const int c4 = i & 31;
            const int tok = k0 + r;
            float4 kv = make_float4(0.f, 0.f, 0.f, 0.f);
            float4 vv = make_float4(0.f, 0.f, 0.f, 0.f);
            if (tok < L) {
                kv = *(const float4*)(kbase + (size_t)tok * KSTRIDE + c4 * 4);
                vv = *(const float4*)(vbase + (size_t)tok * KSTRIDE + c4 * 4);
            }
            uint4 kt, vt;
            kt.x = cvt_tf32(kv.x); kt.y = cvt_tf32(kv.y);
            kt.z = cvt_tf32(kv.z); kt.w = cvt_tf32(kv.w);
            vt.x = cvt_tf32(vv.x); vt.y = cvt_tf32(vv.y);
            vt.z = cvt_tf32(vv.z); vt.w = cvt_tf32(vv.w);
            *(uint4*)(Ks + r * KPAD + c4 * 4) = kt;
            *(uint4*)(Vs + r * VPAD + c4 * 4) = vt;
        }
        __syncthreads();

        // per-warp causal cap: columns > wrow_max - k0 are fully masked for this warp
        const int cap  = wrow_max - k0;            // >= 15 by construction
        const int ntmax = (cap >> 3) + 1;          // # of 8-col tiles needed (<= 8)

        // ---- S = Q K^T : ks-outer, nt-inner (independent chains) ----
        float s[8][4];
        #pragma unroll
        for (int nt = 0; nt < 8; nt++)
            s[nt][0] = s[nt][1] = s[nt][2] = s[nt][3] = 0.f;
        #pragma unroll
        for (int ks = 0; ks < 16; ks++) {
            const float* kb = Ks + g * KPAD + tig + ks * 8;
            #pragma unroll
            for (int nt = 0; nt < 8; nt++) {
                if (nt < ntmax) {
                    uint32_t b[2];
                    b[0] = __float_as_uint(kb[nt * 8 * KPAD]);
                    b[1] = __float_as_uint(kb[nt * 8 * KPAD + 4]);
                    mma_tf32(s[nt], qa[ks], b);
                }
            }
        }

        // ---- mask + exp2 -> P (tf32) into per-warp smem; accumulate l ----
        #pragma unroll
        for (int nt = 0; nt < 8; nt++) {
            if (nt < ntmax) {
                const int cbase = k0 + nt * 8 + tig * 2;
                #pragma unroll
                for (int r = 0; r < 4; r++) {
                    const int col  = cbase + (r & 1);
                    const int qrow = (r & 2) ? qrow1 : qrow0;
                    float p = (col <= qrow) ? exp2f_fast(s[nt][r]) : 0.f;
                    if (r & 2) lsum1 += p; else lsum0 += p;
                    const int prow = (r & 2) ? g + 8 : g;
                    Ps[prow * PPAD + nt * 8 + tig * 2 + (r & 1)] =
                        __uint_as_float(cvt_tf32(p));
                }
            }
        }
        __syncwarp();

        // ---- O += P V : k-steps capped at ntmax ----
        #pragma unroll
        for (int ks = 0; ks < 8; ks++) {
            if (ks < ntmax) {
                uint32_t a[4];
                const int kc = ks * 8 + tig;
                a[0] = __float_as_uint(Ps[g * PPAD + kc]);
                a[1] = __float_as_uint(Ps[(g + 8) * PPAD + kc]);
                a[2] = __float_as_uint(Ps[g * PPAD + kc + 4]);
                a[3] = __float_as_uint(Ps[(g + 8) * PPAD + kc + 4]);
                const float* vb = Vs + (ks * 8 + tig) * VPAD + g;
                #pragma unroll
                for (int nt = 0; nt < 16; nt++) {
                    uint32_t b[2];
                    b[0] = __float_as_uint(vb[nt * 8]);
                    b[1] = __float_as_uint(vb[nt * 8 + 4 * VPAD]);
                    mma_tf32(o[nt], a, b);
                }
            }
        }
        __syncwarp();   // P consumed before next tile overwrites
    }

    // ---- reduce l across quad, normalize, store ----
    #pragma unroll
    for (int off = 1; off < 4; off <<= 1) {
        lsum0 += __shfl_xor_sync(0xffffffffu, lsum0, off);
        lsum1 += __shfl_xor_sync(0xffffffffu, lsum1, off);
    }
    const float inv0 = 1.0f / lsum0;
    const float inv1 = 1.0f / lsum1;

    float* ob0 = out + (size_t)(s0 + qrow0) * QSTRIDE + head * DH;
    float* ob1 = out + (size_t)(s0 + qrow1) * QSTRIDE + head * DH;
    const bool ok0 = qrow0 < L, ok1 = qrow1 < L;
    #pragma unroll
    for (int nt = 0; nt < 16; nt++) {
        const int c = nt * 8 + tig * 2;
        if (ok0) *(float2*)(ob0 + c) = make_float2(o[nt][0] * inv0, o[nt][1] * inv0);
        if (ok1) *(float2*)(ob1 + c) = make_float2(o[nt][2] * inv1, o[nt][3] * inv1);
    }
}

extern "C" void kernel_launch(void* const* d_in, const int* in_sizes, int n_in,
                              void* d_out, int out_size)
{
    const float* q  = (const float*)d_in[0];
    const float* k  = (const float*)d_in[1];
    const float* v  = (const float*)d_in[2];
    const int*   cu = (const int*)d_in[3];

    const int T = in_sizes[0] / QSTRIDE;
    const int B = in_sizes[3] - 1;
    const int qtiles = (T + TQ - 1) / TQ;

    cudaFuncSetAttribute(fa_tf32_mma_kernel,
                         cudaFuncAttributeMaxDynamicSharedMemorySize, SMEM_BYTES);

    dim3 grid(qtiles, 32, B);
    fa_tf32_mma_kernel<<<grid, NT, SMEM_BYTES>>>(q, k, v, cu, (float*)d_out);
}